// round 15
// baseline (speedup 1.0000x reference)
#include <cuda_runtime.h>
#include <cstdint>

#define BATCH 4
#define SEQ   2048
#define DMODEL 512
#define NHEAD 8
#define DHEAD 64
#define NKT  (SEQ / 64)  // 32 k-tiles

// Scratch (allocation-free rule: __device__ globals)
__device__ float g_q[(size_t)BATCH * SEQ * DMODEL];
__device__ float g_k[(size_t)BATCH * SEQ * DMODEL];
__device__ float g_v[(size_t)BATCH * SEQ * DMODEL];
__device__ float g_a[(size_t)BATCH * SEQ * DMODEL];
__device__ float g_wt[(size_t)4 * DMODEL * DMODEL];   // transposed tf32 weights

__device__ __forceinline__ float to_tf32(float x) {
    asm("cvt.rna.tf32.f32 %0, %0;" : "+f"(x));
    return x;
}
__device__ __forceinline__ unsigned f2u(float x) { return __float_as_uint(x); }
__device__ __forceinline__ unsigned s2u(const void* p) {
    return (unsigned)__cvta_generic_to_shared(p);
}

__device__ __forceinline__ void mma_tf32(float c[4], const unsigned a[4],
                                         unsigned b0, unsigned b1)
{
    asm volatile(
        "mma.sync.aligned.m16n8k8.row.col.f32.tf32.tf32.f32 "
        "{%0,%1,%2,%3}, {%4,%5,%6,%7}, {%8,%9}, {%0,%1,%2,%3};\n"
        : "+f"(c[0]), "+f"(c[1]), "+f"(c[2]), "+f"(c[3])
        : "r"(a[0]), "r"(a[1]), "r"(a[2]), "r"(a[3]), "r"(b0), "r"(b1));
}

__device__ __forceinline__ void ldsm4(unsigned r[4], unsigned addr) {
    asm volatile("ldmatrix.sync.aligned.m8n8.x4.shared.b16 {%0,%1,%2,%3}, [%4];"
        : "=r"(r[0]), "=r"(r[1]), "=r"(r[2]), "=r"(r[3]) : "r"(addr));
}

#define CP16(dst, src) \
    asm volatile("cp.async.cg.shared.global [%0], [%1], 16;" :: "r"(dst), "l"(src))
#define CP_COMMIT()  asm volatile("cp.async.commit_group;")
#define CP_WAIT0()   asm volatile("cp.async.wait_group 0;" ::: "memory")
#define CP_WAIT1()   asm volatile("cp.async.wait_group 1;" ::: "memory")

// ----------------------------------------------------------------------------
// prep_w: transpose + tf32-round weights.  out[n][k] = tf32(W[k][n])
// ----------------------------------------------------------------------------
__global__ void prep_w(const float* __restrict__ W0, const float* __restrict__ W1,
                       const float* __restrict__ W2, const float* __restrict__ W3,
                       float* __restrict__ O)
{
    __shared__ float t[32][33];
    const float* W = (blockIdx.z == 0) ? W0 : (blockIdx.z == 1) ? W1
                   : (blockIdx.z == 2) ? W2 : W3;
    float* out = O + (size_t)blockIdx.z * DMODEL * DMODEL;
    const int bx = blockIdx.x * 32, by = blockIdx.y * 32;
    const int tx = threadIdx.x, ty = threadIdx.y;
#pragma unroll
    for (int i = 0; i < 32; i += 8)
        t[ty + i][tx] = W[(size_t)(by + ty + i) * DMODEL + bx + tx];
    __syncthreads();
#pragma unroll
    for (int i = 0; i < 32; i += 8)
        out[(size_t)(bx + ty + i) * DMODEL + by + tx] = to_tf32(t[tx][ty + i]);
}

// ----------------------------------------------------------------------------
// gemm4 (round-14, proven): tf32 GEMM + bias, BK=32, 3-stage cp.async.
// ----------------------------------------------------------------------------
#define GA_STRIDE 36
#define GA_STAGE  (128 * GA_STRIDE)
#define GW_STAGE  (64 * GA_STRIDE)
#define GEMM_SMEM_FLOATS (3 * (GA_STAGE + GW_STAGE))

template<bool ROUND>
__device__ __forceinline__ void gemm4_body(
    const float* __restrict__ A, const float* __restrict__ Wt,
    const float* __restrict__ bias, float* __restrict__ C, float scale)
{
    extern __shared__ float gsh[];
    float* As = gsh;
    float* Ws = gsh + 3 * GA_STAGE;

    const int tid = threadIdx.x;
    const int lane = tid & 31, warp = tid >> 5;
    const int mw = (warp >> 1) * 32;
    const int nw = (warp & 1) * 32;
    const int r = lane >> 2, c = lane & 3;

    float acc[2][4][4];
#pragma unroll
    for (int i = 0; i < 2; i++)
#pragma unroll
        for (int j = 0; j < 4; j++)
#pragma unroll
            for (int k = 0; k < 4; k++) acc[i][j][k] = 0.f;

    const float* Ab = A + (size_t)blockIdx.y * 128 * 512;
    const float* Wb = Wt + (size_t)blockIdx.x * 64 * 512;

    const unsigned uA = s2u(As);
    const unsigned uW = s2u(Ws);

    auto issue = [&](int k0, int s) {
#pragma unroll
        for (int i = 0; i < 4; i++) {
            int f = tid + 256 * i;
            int row = f >> 3, c4 = f & 7;
            CP16(uA + (unsigned)(s * GA_STAGE * 4) +
                     (unsigned)(row * GA_STRIDE + c4 * 4) * 4,
                 Ab + (size_t)row * 512 + k0 + c4 * 4);
        }
#pragma unroll
        for (int i = 0; i < 2; i++) {
            int f = tid + 256 * i;
            int row = f >> 3, c4 = f & 7;
            CP16(uW + (unsigned)(s * GW_STAGE * 4) +
                     (unsigned)(row * GA_STRIDE + c4 * 4) * 4,
                 Wb + (size_t)row * 512 + k0 + c4 * 4);
        }
    };

    const unsigned fA = ((mw + (lane & 15)) * GA_STRIDE + ((lane >> 4) << 2)) * 4;
    const unsigned fB = ((nw + (lane & 7) + ((lane >> 4) << 3)) * GA_STRIDE +
                        (((lane >> 3) & 1) << 2)) * 4;

    issue(0, 0);  CP_COMMIT();
    issue(32, 1); CP_COMMIT();
    CP_WAIT1();
    __syncthreads();

#pragma unroll 1
    for (int t = 0; t < 16; ++t) {
        const int s = t % 3;
        const unsigned aBase = uA + (unsigned)(s * GA_STAGE * 4) + fA;
        const unsigned bBase = uW + (unsigned)(s * GW_STAGE * 4) + fB;
#pragma unroll
        for (int ks = 0; ks < 32; ks += 8) {
            unsigned a0[4], a1[4], bF[4];
            ldsm4(a0, aBase + ks * 4);
            ldsm4(a1, aBase + 16 * GA_STRIDE * 4 + ks * 4);
#pragma unroll
            for (int j = 0; j < 4; j++) {
                a0[j] = f2u(to_tf32(__uint_as_float(a0[j])));
                a1[j] = f2u(to_tf32(__uint_as_float(a1[j])));
            }
            ldsm4(bF, bBase + ks * 4);
            mma_tf32(acc[0][0], a0, bF[0], bF[1]);
            mma_tf32(acc[0][1], a0, bF[2], bF[3]);
            mma_tf32(acc[1][0], a1, bF[0], bF[1]);
            mma_tf32(acc[1][1], a1, bF[2], bF[3]);
            ldsm4(bF, bBase + 16 * GA_STRIDE * 4 + ks * 4);
            mma_tf32(acc[0][2], a0, bF[0], bF[1]);
            mma_tf32(acc[0][3], a0, bF[2], bF[3]);
            mma_tf32(acc[1][2], a1, bF[0], bF[1]);
            mma_tf32(acc[1][3], a1, bF[2], bF[3]);
        }
        if (t + 2 < 16) issue((t + 2) * 32, (t + 2) % 3);
        CP_COMMIT();
        CP_WAIT1();
        __syncthreads();
    }

#pragma unroll
    for (int mt = 0; mt < 2; mt++)
#pragma unroll
    for (int nt = 0; nt < 4; nt++) {
        int col = blockIdx.x * 64 + nw + nt * 8 + 2 * c;
        float bx = __ldg(bias + col), by = __ldg(bias + col + 1);
        size_t row0 = blockIdx.y * 128 + mw + mt * 16 + r;
        float v0 = acc[mt][nt][0] + bx, v1 = acc[mt][nt][1] + by;
        float v2 = acc[mt][nt][2] + bx, v3 = acc[mt][nt][3] + by;
        if (ROUND) {
            v0 = to_tf32(v0 * scale); v1 = to_tf32(v1 * scale);
            v2 = to_tf32(v2 * scale); v3 = to_tf32(v3 * scale);
        }
        *(float2*)(C + row0 * 512 + col) = make_float2(v0, v1);
        *(float2*)(C + (row0 + 8) * 512 + col) = make_float2(v2, v3);
    }
}

__global__ void __launch_bounds__(256) gemm_qkv4(
    const float* __restrict__ Aq, const float* __restrict__ Ak,
    const float* __restrict__ Av, const float* __restrict__ Wt,
    const float* __restrict__ bq, const float* __restrict__ bk,
    const float* __restrict__ bv,
    float* __restrict__ Cq, float* __restrict__ Ck, float* __restrict__ Cv)
{
    const int z = blockIdx.z;
    const float* A = (z == 0) ? Aq : (z == 1) ? Ak : Av;
    const float* W = Wt + (size_t)z * DMODEL * DMODEL;
    const float* bb = (z == 0) ? bq : (z == 1) ? bk : bv;
    float* C = (z == 0) ? Cq : (z == 1) ? Ck : Cv;
    gemm4_body<true>(A, W, bb, C, (z == 0) ? 0.125f : 1.f);
}

__global__ void __launch_bounds__(256) gemm_o4(
    const float* __restrict__ A, const float* __restrict__ Wt,
    const float* __restrict__ bias, float* __restrict__ C)
{
    gemm4_body<false>(A, Wt, bias, C, 1.f);
}

// ----------------------------------------------------------------------------
// Flash attention v14 = round-14 attn11 + coalesced weights store:
// exact fp32 p staged in P smem; cooperative float4 tile write to wts;
// PV A-frags rounded post-ldsm (same RNA point -> bit-identical numerics).
// Smem floats: Q[4352] K0[4352] K1[4352] V[4608] P[4352] stats[256] = 22272
// ----------------------------------------------------------------------------
#define QSTR 68
#define VSTR 72
#define OFF_K0 4352
#define OFF_K1 8704
#define OFF_V  13056
#define OFF_P  17664
#define OFF_ST 22016
#define ATTN_SMEM_FLOATS 22272
#define APD ((OFF_K1 - OFF_K0) * 4)   // K buffer byte delta

__global__ void __launch_bounds__(256) attn14(
    const float* __restrict__ mask, float* __restrict__ wts)
{
    extern __shared__ float sh[];
    float* statsf = sh + OFF_ST;

    const int tid = threadIdx.x;
    const int lane = tid & 31, warp = tid >> 5;
    const int mw = (warp >> 1) * 16;
    const int nwi = warp & 1;
    const int nw = nwi * 32;
    const int r = lane >> 2, c = lane & 3;

    const int qt = blockIdx.x, bh = blockIdx.y;
    const int b = bh >> 3, h = bh & 7;
    const int q0 = qt * 64;

    const float* qg = g_q + ((size_t)(b * SEQ + q0)) * DMODEL + h * DHEAD;
    const float* kg = g_k + (size_t)b * SEQ * DMODEL + h * DHEAD;
    const float* vg = g_v + (size_t)b * SEQ * DMODEL + h * DHEAD;
    const float2* mb2 = (const float2*)(mask + (size_t)b * SEQ);
    float* wb = wts + ((size_t)bh * SEQ + q0) * SEQ;

    const unsigned uQst = s2u(sh);
    const unsigned uKst = s2u(sh + OFF_K0);
    const unsigned uVst = s2u(sh + OFF_V);

    // prologue: Q + K0
#pragma unroll
    for (int i = 0; i < 4; i++) {
        int f = tid + 256 * i;
        int row = f >> 4, c4 = f & 15;
        CP16(uQst + (unsigned)(row * QSTR + c4 * 4) * 4,
             qg + (size_t)row * DMODEL + c4 * 4);
        CP16(uKst + (unsigned)(row * QSTR + c4 * 4) * 4,
             kg + (size_t)row * DMODEL + c4 * 4);
    }
    CP_COMMIT();
    CP_WAIT0();
    __syncthreads();

    // hoist Q fragments into registers (once, reused across both passes)
    unsigned qf[8][4];
    {
        const unsigned uQ = uQst +
            (((mw + (lane & 15)) * QSTR) + ((lane >> 4) << 2)) * 4;
#pragma unroll
        for (int kq = 0; kq < 8; kq++)
            ldsm4(qf[kq], uQ + kq * 32);
    }

    const unsigned uPfr = s2u(sh + OFF_P) +
        (((mw + (lane & 15)) * QSTR) + ((lane >> 4) << 2)) * 4;
    unsigned uK[2];
#pragma unroll
    for (int ntp = 0; ntp < 2; ntp++)
        uK[ntp] = uKst +
            (((nw + ntp * 16 + (lane & 7) + ((lane >> 4) << 3)) * QSTR) +
             (((lane >> 3) & 1) << 2)) * 4;

    float l0 = 0.f, l1 = 0.f;

    // ======================= Pass A: QK -> sum exp =======================
#pragma unroll 1
    for (int kt = 0; kt < NKT; ++kt) {
        const unsigned cd = (kt & 1) ? APD : 0u;
        if (kt + 1 < NKT) {
            const unsigned nd = ((kt + 1) & 1) ? APD : 0u;
            const float* src = kg + (size_t)(kt + 1) * 64 * DMODEL;
#pragma unroll
            for (int i = 0; i < 4; i++) {
                int f = tid + 256 * i;
                int row = f >> 4, c4 = f & 15;
                CP16(uKst + nd + (unsigned)(row * QSTR + c4 * 4) * 4,
                     src + (size_t)row * DMODEL + c4 * 4);
            }
            CP_COMMIT();
        }

        float sf[4][4];
#pragma unroll
        for (int nt = 0; nt < 4; nt++)
#pragma unroll
            for (int j = 0; j < 4; j++) sf[nt][j] = 0.f;

#pragma unroll
        for (int kq = 0; kq < 8; kq++) {
            unsigned bF[4];
            ldsm4(bF, uK[0] + cd + kq * 32);
            mma_tf32(sf[0], qf[kq], bF[0], bF[1]);
            mma_tf32(sf[1], qf[kq], bF[2], bF[3]);
            ldsm4(bF, uK[1] + cd + kq * 32);
            mma_tf32(sf[2], qf[kq], bF[0], bF[1]);
            mma_tf32(sf[3], qf[kq], bF[2], bF[3]);
        }

        // accumulate per-thread partial sums only (reduction deferred)
#pragma unroll
        for (int nt = 0; nt < 4; nt++) {
            int col = nw + nt * 8 + 2 * c;
            float2 mv = __ldg(&mb2[(kt * 64 + col) >> 1]);
            float mk0 = mv.x * -1e9f, mk1 = mv.y * -1e9f;
            l0 += __expf(sf[nt][0] + mk0) + __expf(sf[nt][1] + mk1);
            l1 += __expf(sf[nt][2] + mk0) + __expf(sf[nt][3] + mk1);
        }

        CP_WAIT0();
        __syncthreads();
    }

    // deferred quad reduction (once)
    l0 += __shfl_xor_sync(0xffffffffu, l0, 1);
    l0 += __shfl_xor_sync(0xffffffffu, l0, 2);
    l1 += __shfl_xor_sync(0xffffffffu, l1, 1);
    l1 += __shfl_xor_sync(0xffffffffu, l1, 2);
    if (c == 0) {
        statsf[(mw + r) * 2 + nwi] = l0;
        statsf[(mw + r + 8) * 2 + nwi] = l1;
    }

    // pass-B prologue: K(0) -> buffer 0
#pragma unroll
    for (int i = 0; i < 4; i++) {
        int f = tid + 256 * i;
        int row = f >> 4, c4 = f & 15;
        CP16(uKst + (unsigned)(row * QSTR + c4 * 4) * 4,
             kg + (size_t)row * DMODEL + c4 * 4);
    }
    CP_COMMIT();
    CP_WAIT0();
    __syncthreads();   // K(0) + statsf visible

    const float il0 = 1.f / (statsf[(mw + r) * 2] + statsf[(mw + r) * 2 + 1]);
    const float il1 = 1.f / (statsf[(mw + r + 8) * 2] + statsf[(mw + r + 8) * 2 + 1]);

    // ======================= Pass B: weights + PV =======================
    float of[4][4];
#pragma unroll
    for (int nt = 0; nt < 4; nt++)
#pragma unroll
        for (int j = 0; j < 4; j++) of[nt][j] = 0.f;

    float* Pp = sh + OFF_P;

#pragma unroll 1
    for (int kt = 0; kt < NKT; ++kt) {
        const unsigned cd = (kt & 1) ? APD : 0u;
        const bool haveK = (kt + 1 < NKT);

        // top: issue V(kt) [group V], then K(kt+1) -> alt buffer [group K]
        {
            const float* vsrc = vg + (size_t)kt * 64 * DMODEL;
#pragma unroll
            for (int i = 0; i < 4; i++) {
                int f = tid + 256 * i;
                int row = f >> 4, c4 = f & 15;
                CP16(uVst + (unsigned)(row * VSTR + c4 * 4) * 4,
                     vsrc + (size_t)row * DMODEL + c4 * 4);
            }
            CP_COMMIT();
        }
        if (haveK) {
            const unsigned nd = ((kt + 1) & 1) ? APD : 0u;
            const float* ksrc = kg + (size_t)(kt + 1) * 64 * DMODEL;
#pragma unroll
            for (int i = 0; i < 4; i++) {
                int f = tid + 256 * i;
                int row = f >> 4, c4 = f & 15;
                CP16(uKst + nd + (unsigned)(row * QSTR + c4 * 4) * 4,
                     ksrc + (size_t)row * DMODEL + c4 * 4);
            }
            CP_COMMIT();
        }

        // QK from K(kt)
        float sf[4][4];
#pragma unroll
        for (int nt = 0; nt < 4; nt++)
#pragma unroll
            for (int j = 0; j < 4; j++) sf[nt][j] = 0.f;
#pragma unroll
        for (int kq = 0; kq < 8; kq++) {
            unsigned bF[4];
            ldsm4(bF, uK[0] + cd + kq * 32);
            mma_tf32(sf[0], qf[kq], bF[0], bF[1]);
            mma_tf32(sf[1], qf[kq], bF[2], bF[3]);
            ldsm4(bF, uK[1] + cd + kq * 32);
            mma_tf32(sf[2], qf[kq], bF[0], bF[1]);
            mma_tf32(sf[3], qf[kq], bF[2], bF[3]);
        }

        // weights: exact fp32 p into P smem only (global write deferred)
#pragma unroll
        for (int nt = 0; nt < 4; nt++) {
            int col = nw + nt * 8 + 2 * c;
            float2 mv = __ldg(&mb2[(kt * 64 + col) >> 1]);
            float mk0 = mv.x * -1e9f, mk1 = mv.y * -1e9f;
            float p0 = __expf(sf[nt][0] + mk0) * il0;
            float p1 = __expf(sf[nt][1] + mk1) * il0;
            float p2 = __expf(sf[nt][2] + mk0) * il1;
            float p3 = __expf(sf[nt][3] + mk1) * il1;
            *(float2*)&Pp[(mw + r) * QSTR + col] = make_float2(p0, p1);
            *(float2*)&Pp[(mw + r + 8) * QSTR + col] = make_float2(p2, p3);
        }

        // mid: drain V group only (K group keeps flying through PV)
        if (haveK) { CP_WAIT1(); } else { CP_WAIT0(); }
        __syncthreads();   // V(kt) + P visible; QK reads of K done

        // coalesced weights store from P smem (64 rows x 256B)
#pragma unroll
        for (int i = 0; i < 4; i++) {
            int f = tid + 256 * i;
            int row = (f >> 4) + i * 0;        // rows 0..63 over 4 iters
            int rr = f >> 4, c4 = f & 15;
            (void)row;
            float4 v = *(float4*)&Pp[rr * QSTR + c4 * 4];
            *(float4*)(wb + (size_t)rr * SEQ + kt * 64 + c4 * 4) = v;
        }

        // PV: O += P @ V ; A-frags rounded post-ldsm (same RNA point)
        const float* Vs_ = sh + OFF_V;
#pragma unroll
        for (int ks = 0; ks < 64; ks += 8) {
            unsigned a[4];
            ldsm4(a, uPfr + ks * 4);
#pragma unroll
            for (int j = 0; j < 4; j++)
                a[j] = f2u(to_tf32(__uint_as_float(a[j])));
            const float* Vr0 = Vs_ + (ks + c) * VSTR + nw;
            const float* Vr1 = Vs_ + (ks + c + 4) * VSTR + nw;
#pragma unroll
            for (int nt = 0; nt < 4; nt++) {
                unsigned b0 = f2u(Vr0[nt * 8 + r]);
                unsigned b1 = f2u(Vr1[nt * 8 + r]);
                mma_tf32(of[nt], a, b0, b1);
            }
        }

        // end: drain K(kt+1); barrier frees V/P buffers for next tile
        if (haveK) {
            CP_WAIT0();
            __syncthreads();
        }
    }

    // direct O store
    float* ab = g_a + ((size_t)(b * SEQ + q0 + mw + r)) * DMODEL + h * DHEAD;
#pragma unroll
    for (int nt = 0; nt < 4; nt++) {
        int col = nw + nt * 8 + 2 * c;
        *(float2*)(ab + col) = make_float2(of[nt][0], of[nt][1]);
        *(float2*)(ab + (size_t)8 * DMODEL + col) =
            make_float2(of[nt][2], of[nt][3]);
    }
}

// NOTE: weights rows handled per iteration: f>>4 gives 0..15 for i=0... need
// full 64 rows; handled by f = tid + 256*i -> f>>4 spans 0..63 across i. (ok)

// ----------------------------------------------------------------------------
extern "C" void kernel_launch(void* const* d_in, const int* in_sizes, int n_in,
                              void* d_out, int out_size)
{
    const float* Q    = (const float*)d_in[0];
    const float* K    = (const float*)d_in[1];
    const float* V    = (const float*)d_in[2];
    const float* mask = (const float*)d_in[3];
    const float* Wq_w = (const float*)d_in[4];
    const float* Wq_b = (const float*)d_in[5];
    const float* Wk_w = (const float*)d_in[6];
    const float* Wk_b = (const float*)d_in[7];
    const float* Wv_w = (const float*)d_in[8];
    const float* Wv_b = (const float*)d_in[9];
    const float* Wo_w = (const float*)d_in[10];
    const float* Wo_b = (const float*)d_in[11];

    float* out = (float*)d_out;
    float* wts = out + (size_t)BATCH * SEQ * DMODEL;

    float *qb, *kb, *vb, *ab, *wt;
    cudaGetSymbolAddress((void**)&qb, g_q);
    cudaGetSymbolAddress((void**)&kb, g_k);
    cudaGetSymbolAddress((void**)&vb, g_v);
    cudaGetSymbolAddress((void**)&ab, g_a);
    cudaGetSymbolAddress((void**)&wt, g_wt);

    const int attn_smem = ATTN_SMEM_FLOATS * 4;   // 89088 B
    cudaFuncSetAttribute(attn14,
                         cudaFuncAttributeMaxDynamicSharedMemorySize, attn_smem);
    const int gemm_smem = GEMM_SMEM_FLOATS * 4;   // 82944 B
    cudaFuncSetAttribute(gemm_qkv4,
                         cudaFuncAttributeMaxDynamicSharedMemorySize, gemm_smem);
    cudaFuncSetAttribute(gemm_o4,
                         cudaFuncAttributeMaxDynamicSharedMemorySize, gemm_smem);

    prep_w<<<dim3(16, 16, 4), dim3(32, 8)>>>(Wq_w, Wk_w, Wv_w, Wo_w, wt);

    dim3 gqkv(512 / 64, (BATCH * SEQ) / 128, 3);
    gemm_qkv4<<<gqkv, 256, gemm_smem>>>(Q, K, V, wt, Wq_b, Wk_b, Wv_b,
                                        qb, kb, vb);

    attn14<<<dim3(SEQ / 64, BATCH * NHEAD), 256, attn_smem>>>(mask, wts);

    dim3 gg(512 / 64, (BATCH * SEQ) / 128);
    gemm_o4<<<gg, 256, gemm_smem>>>(ab, wt + (size_t)3 * DMODEL * DMODEL,
                                    Wo_b, out);
}

// round 16
// speedup vs baseline: 1.0137x; 1.0137x over previous
#include <cuda_runtime.h>
#include <cstdint>

#define BATCH 4
#define SEQ   2048
#define DMODEL 512
#define NHEAD 8
#define DHEAD 64
#define NKT  (SEQ / 64)  // 32 k-tiles

// Scratch (allocation-free rule: __device__ globals)
__device__ float g_q[(size_t)BATCH * SEQ * DMODEL];
__device__ float g_k[(size_t)BATCH * SEQ * DMODEL];
__device__ float g_v[(size_t)BATCH * SEQ * DMODEL];
__device__ float g_a[(size_t)BATCH * SEQ * DMODEL];
__device__ float g_wt[(size_t)4 * DMODEL * DMODEL];   // transposed tf32 weights

__device__ __forceinline__ float to_tf32(float x) {
    asm("cvt.rna.tf32.f32 %0, %0;" : "+f"(x));
    return x;
}
__device__ __forceinline__ unsigned f2u(float x) { return __float_as_uint(x); }
__device__ __forceinline__ unsigned s2u(const void* p) {
    return (unsigned)__cvta_generic_to_shared(p);
}

__device__ __forceinline__ void mma_tf32(float c[4], const unsigned a[4],
                                         unsigned b0, unsigned b1)
{
    asm volatile(
        "mma.sync.aligned.m16n8k8.row.col.f32.tf32.tf32.f32 "
        "{%0,%1,%2,%3}, {%4,%5,%6,%7}, {%8,%9}, {%0,%1,%2,%3};\n"
        : "+f"(c[0]), "+f"(c[1]), "+f"(c[2]), "+f"(c[3])
        : "r"(a[0]), "r"(a[1]), "r"(a[2]), "r"(a[3]), "r"(b0), "r"(b1));
}

__device__ __forceinline__ void ldsm4(unsigned r[4], unsigned addr) {
    asm volatile("ldmatrix.sync.aligned.m8n8.x4.shared.b16 {%0,%1,%2,%3}, [%4];"
        : "=r"(r[0]), "=r"(r[1]), "=r"(r[2]), "=r"(r[3]) : "r"(addr));
}

#define CP16(dst, src) \
    asm volatile("cp.async.cg.shared.global [%0], [%1], 16;" :: "r"(dst), "l"(src))
#define CP_COMMIT()  asm volatile("cp.async.commit_group;")
#define CP_WAIT0()   asm volatile("cp.async.wait_group 0;" ::: "memory")
#define CP_WAIT1()   asm volatile("cp.async.wait_group 1;" ::: "memory")

// ----------------------------------------------------------------------------
// prep_w: transpose + tf32-round weights.  out[n][k] = tf32(W[k][n])
// ----------------------------------------------------------------------------
__global__ void prep_w(const float* __restrict__ W0, const float* __restrict__ W1,
                       const float* __restrict__ W2, const float* __restrict__ W3,
                       float* __restrict__ O)
{
    __shared__ float t[32][33];
    const float* W = (blockIdx.z == 0) ? W0 : (blockIdx.z == 1) ? W1
                   : (blockIdx.z == 2) ? W2 : W3;
    float* out = O + (size_t)blockIdx.z * DMODEL * DMODEL;
    const int bx = blockIdx.x * 32, by = blockIdx.y * 32;
    const int tx = threadIdx.x, ty = threadIdx.y;
#pragma unroll
    for (int i = 0; i < 32; i += 8)
        t[ty + i][tx] = W[(size_t)(by + ty + i) * DMODEL + bx + tx];
    __syncthreads();
#pragma unroll
    for (int i = 0; i < 32; i += 8)
        out[(size_t)(bx + ty + i) * DMODEL + by + tx] = to_tf32(t[tx][ty + i]);
}

// ----------------------------------------------------------------------------
// gemm5: tf32 GEMM + bias, BM=128, BN=128, BK=32, 2-stage cp.async.
// 8 warps (4m x 2n), warp tile 32x64: per 8-k step 6 ldsm feed 32 mma.
// Smem: 2 stages x (A 128*36 + W 128*36) = 18432 floats (72KB).
// ----------------------------------------------------------------------------
#define G5_STRIDE 36
#define G5_ATILE  (128 * G5_STRIDE)          // 4608 floats
#define G5_STAGE  (2 * G5_ATILE)             // A + W per stage
#define GEMM5_SMEM_FLOATS (2 * G5_STAGE)

template<bool ROUND>
__device__ __forceinline__ void gemm5_body(
    const float* __restrict__ A, const float* __restrict__ Wt,
    const float* __restrict__ bias, float* __restrict__ C, float scale)
{
    extern __shared__ float gsh[];

    const int tid = threadIdx.x;
    const int lane = tid & 31, warp = tid >> 5;
    const int mw = (warp >> 1) * 32;
    const int nw = (warp & 1) * 64;
    const int r = lane >> 2, c = lane & 3;

    float acc[2][8][4];
#pragma unroll
    for (int i = 0; i < 2; i++)
#pragma unroll
        for (int j = 0; j < 8; j++)
#pragma unroll
            for (int k = 0; k < 4; k++) acc[i][j][k] = 0.f;

    const float* Ab = A + (size_t)blockIdx.y * 128 * 512;
    const float* Wb = Wt + (size_t)blockIdx.x * 128 * 512;

    const unsigned uBase = s2u(gsh);

    auto issue = [&](int k0, int s) {
        const unsigned sb = uBase + (unsigned)(s * G5_STAGE * 4);
#pragma unroll
        for (int i = 0; i < 4; i++) {           // A: 128x32 = 1024 float4
            int f = tid + 256 * i;
            int row = f >> 3, c4 = f & 7;
            CP16(sb + (unsigned)(row * G5_STRIDE + c4 * 4) * 4,
                 Ab + (size_t)row * 512 + k0 + c4 * 4);
        }
#pragma unroll
        for (int i = 0; i < 4; i++) {           // W: 128x32 = 1024 float4
            int f = tid + 256 * i;
            int row = f >> 3, c4 = f & 7;
            CP16(sb + (unsigned)(G5_ATILE * 4) +
                     (unsigned)(row * G5_STRIDE + c4 * 4) * 4,
                 Wb + (size_t)row * 512 + k0 + c4 * 4);
        }
    };

    const unsigned fA = ((mw + (lane & 15)) * G5_STRIDE + ((lane >> 4) << 2)) * 4;
    const unsigned fB0 = (unsigned)(G5_ATILE * 4) +
        ((nw + (lane & 7) + ((lane >> 4) << 3)) * G5_STRIDE +
         (((lane >> 3) & 1) << 2)) * 4;

    issue(0, 0);
    CP_COMMIT();
    CP_WAIT0();
    __syncthreads();

#pragma unroll 1
    for (int t = 0; t < 16; ++t) {
        const int s = t & 1;
        if (t + 1 < 16) { issue((t + 1) * 32, s ^ 1); CP_COMMIT(); }

        const unsigned sb = uBase + (unsigned)(s * G5_STAGE * 4);
        const unsigned aBase = sb + fA;
        const unsigned bBase = sb + fB0;
#pragma unroll
        for (int ks = 0; ks < 32; ks += 8) {
            unsigned a0[4], a1[4];
            ldsm4(a0, aBase + ks * 4);
            ldsm4(a1, aBase + 16 * G5_STRIDE * 4 + ks * 4);
#pragma unroll
            for (int j = 0; j < 4; j++) {
                a0[j] = f2u(to_tf32(__uint_as_float(a0[j])));
                a1[j] = f2u(to_tf32(__uint_as_float(a1[j])));
            }
#pragma unroll
            for (int half = 0; half < 2; half++) {
                unsigned bF[4];
                ldsm4(bF, bBase + half * 32 * G5_STRIDE * 4 + ks * 4);
                mma_tf32(acc[0][half * 4 + 0], a0, bF[0], bF[1]);
                mma_tf32(acc[0][half * 4 + 1], a0, bF[2], bF[3]);
                mma_tf32(acc[1][half * 4 + 0], a1, bF[0], bF[1]);
                mma_tf32(acc[1][half * 4 + 1], a1, bF[2], bF[3]);
                ldsm4(bF, bBase + (half * 32 + 16) * G5_STRIDE * 4 + ks * 4);
                mma_tf32(acc[0][half * 4 + 2], a0, bF[0], bF[1]);
                mma_tf32(acc[0][half * 4 + 3], a0, bF[2], bF[3]);
                mma_tf32(acc[1][half * 4 + 2], a1, bF[0], bF[1]);
                mma_tf32(acc[1][half * 4 + 3], a1, bF[2], bF[3]);
            }
        }
        CP_WAIT0();
        __syncthreads();
    }

#pragma unroll
    for (int mt = 0; mt < 2; mt++)
#pragma unroll
    for (int nt = 0; nt < 8; nt++) {
        int ncol = (nt >> 2) * 32 + (nt & 3) * 8;      // within warp 64
        int col = blockIdx.x * 128 + nw + ncol + 2 * c;
        float bx = __ldg(bias + col), by = __ldg(bias + col + 1);
        size_t row0 = blockIdx.y * 128 + mw + mt * 16 + r;
        float v0 = acc[mt][nt][0] + bx, v1 = acc[mt][nt][1] + by;
        float v2 = acc[mt][nt][2] + bx, v3 = acc[mt][nt][3] + by;
        if (ROUND) {
            v0 = to_tf32(v0 * scale); v1 = to_tf32(v1 * scale);
            v2 = to_tf32(v2 * scale); v3 = to_tf32(v3 * scale);
        }
        *(float2*)(C + row0 * 512 + col) = make_float2(v0, v1);
        *(float2*)(C + (row0 + 8) * 512 + col) = make_float2(v2, v3);
    }
}

__global__ void __launch_bounds__(256) gemm_qkv5(
    const float* __restrict__ Aq, const float* __restrict__ Ak,
    const float* __restrict__ Av, const float* __restrict__ Wt,
    const float* __restrict__ bq, const float* __restrict__ bk,
    const float* __restrict__ bv,
    float* __restrict__ Cq, float* __restrict__ Ck, float* __restrict__ Cv)
{
    const int z = blockIdx.z;
    const float* A = (z == 0) ? Aq : (z == 1) ? Ak : Av;
    const float* W = Wt + (size_t)z * DMODEL * DMODEL;
    const float* bb = (z == 0) ? bq : (z == 1) ? bk : bv;
    float* C = (z == 0) ? Cq : (z == 1) ? Ck : Cv;
    gemm5_body<true>(A, W, bb, C, (z == 0) ? 0.125f : 1.f);
}

__global__ void __launch_bounds__(256) gemm_o5(
    const float* __restrict__ A, const float* __restrict__ Wt,
    const float* __restrict__ bias, float* __restrict__ C)
{
    gemm5_body<false>(A, Wt, bias, C, 1.f);
}

// ----------------------------------------------------------------------------
// Flash attention (round-14 attn11, best proven): Q-reg-hoisted, deferred
// pass-A reduction, double-buffered K both passes, top-of-tile K prefetch.
// Smem floats: Q[4352] K0[4352] K1[4352] V[4608] P[4352] stats[256] = 22272
// ----------------------------------------------------------------------------
#define QSTR 68
#define VSTR 72
#define OFF_K0 4352
#define OFF_K1 8704
#define OFF_V  13056
#define OFF_P  17664
#define OFF_ST 22016
#define ATTN_SMEM_FLOATS 22272
#define APD ((OFF_K1 - OFF_K0) * 4)   // K buffer byte delta

__global__ void __launch_bounds__(256) attn11(
    const float* __restrict__ mask, float* __restrict__ wts)
{
    extern __shared__ float sh[];
    float* statsf = sh + OFF_ST;

    const int tid = threadIdx.x;
    const int lane = tid & 31, warp = tid >> 5;
    const int mw = (warp >> 1) * 16;
    const int nwi = warp & 1;
    const int nw = nwi * 32;
    const int r = lane >> 2, c = lane & 3;

    const int qt = blockIdx.x, bh = blockIdx.y;
    const int b = bh >> 3, h = bh & 7;
    const int q0 = qt * 64;

    const float* qg = g_q + ((size_t)(b * SEQ + q0)) * DMODEL + h * DHEAD;
    const float* kg = g_k + (size_t)b * SEQ * DMODEL + h * DHEAD;
    const float* vg = g_v + (size_t)b * SEQ * DMODEL + h * DHEAD;
    const float2* mb2 = (const float2*)(mask + (size_t)b * SEQ);
    float* wb = wts + ((size_t)bh * SEQ + q0) * SEQ;

    const unsigned uQst = s2u(sh);
    const unsigned uKst = s2u(sh + OFF_K0);
    const unsigned uVst = s2u(sh + OFF_V);

    // prologue: Q + K0
#pragma unroll
    for (int i = 0; i < 4; i++) {
        int f = tid + 256 * i;
        int row = f >> 4, c4 = f & 15;
        CP16(uQst + (unsigned)(row * QSTR + c4 * 4) * 4,
             qg + (size_t)row * DMODEL + c4 * 4);
        CP16(uKst + (unsigned)(row * QSTR + c4 * 4) * 4,
             kg + (size_t)row * DMODEL + c4 * 4);
    }
    CP_COMMIT();
    CP_WAIT0();
    __syncthreads();

    // hoist Q fragments into registers (once, reused across both passes)
    unsigned qf[8][4];
    {
        const unsigned uQ = uQst +
            (((mw + (lane & 15)) * QSTR) + ((lane >> 4) << 2)) * 4;
#pragma unroll
        for (int kq = 0; kq < 8; kq++)
            ldsm4(qf[kq], uQ + kq * 32);
    }

    const unsigned uPfr = s2u(sh + OFF_P) +
        (((mw + (lane & 15)) * QSTR) + ((lane >> 4) << 2)) * 4;
    unsigned uK[2];
#pragma unroll
    for (int ntp = 0; ntp < 2; ntp++)
        uK[ntp] = uKst +
            (((nw + ntp * 16 + (lane & 7) + ((lane >> 4) << 3)) * QSTR) +
             (((lane >> 3) & 1) << 2)) * 4;

    float l0 = 0.f, l1 = 0.f;

    // ======================= Pass A: QK -> sum exp =======================
#pragma unroll 1
    for (int kt = 0; kt < NKT; ++kt) {
        const unsigned cd = (kt & 1) ? APD : 0u;
        if (kt + 1 < NKT) {
            const unsigned nd = ((kt + 1) & 1) ? APD : 0u;
            const float* src = kg + (size_t)(kt + 1) * 64 * DMODEL;
#pragma unroll
            for (int i = 0; i < 4; i++) {
                int f = tid + 256 * i;
                int row = f >> 4, c4 = f & 15;
                CP16(uKst + nd + (unsigned)(row * QSTR + c4 * 4) * 4,
                     src + (size_t)row * DMODEL + c4 * 4);
            }
            CP_COMMIT();
        }

        float sf[4][4];
#pragma unroll
        for (int nt = 0; nt < 4; nt++)
#pragma unroll
            for (int j = 0; j < 4; j++) sf[nt][j] = 0.f;

#pragma unroll
        for (int kq = 0; kq < 8; kq++) {
            unsigned bF[4];
            ldsm4(bF, uK[0] + cd + kq * 32);
            mma_tf32(sf[0], qf[kq], bF[0], bF[1]);
            mma_tf32(sf[1], qf[kq], bF[2], bF[3]);
            ldsm4(bF, uK[1] + cd + kq * 32);
            mma_tf32(sf[2], qf[kq], bF[0], bF[1]);
            mma_tf32(sf[3], qf[kq], bF[2], bF[3]);
        }

        // accumulate per-thread partial sums only (reduction deferred)
#pragma unroll
        for (int nt = 0; nt < 4; nt++) {
            int col = nw + nt * 8 + 2 * c;
            float2 mv = __ldg(&mb2[(kt * 64 + col) >> 1]);
            float mk0 = mv.x * -1e9f, mk1 = mv.y * -1e9f;
            l0 += __expf(sf[nt][0] + mk0) + __expf(sf[nt][1] + mk1);
            l1 += __expf(sf[nt][2] + mk0) + __expf(sf[nt][3] + mk1);
        }

        CP_WAIT0();
        __syncthreads();
    }

    // deferred quad reduction (once)
    l0 += __shfl_xor_sync(0xffffffffu, l0, 1);
    l0 += __shfl_xor_sync(0xffffffffu, l0, 2);
    l1 += __shfl_xor_sync(0xffffffffu, l1, 1);
    l1 += __shfl_xor_sync(0xffffffffu, l1, 2);
    if (c == 0) {
        statsf[(mw + r) * 2 + nwi] = l0;
        statsf[(mw + r + 8) * 2 + nwi] = l1;
    }

    // pass-B prologue: K(0) -> buffer 0
#pragma unroll
    for (int i = 0; i < 4; i++) {
        int f = tid + 256 * i;
        int row = f >> 4, c4 = f & 15;
        CP16(uKst + (unsigned)(row * QSTR + c4 * 4) * 4,
             kg + (size_t)row * DMODEL + c4 * 4);
    }
    CP_COMMIT();
    CP_WAIT0();
    __syncthreads();   // K(0) + statsf visible

    const float il0 = 1.f / (statsf[(mw + r) * 2] + statsf[(mw + r) * 2 + 1]);
    const float il1 = 1.f / (statsf[(mw + r + 8) * 2] + statsf[(mw + r + 8) * 2 + 1]);

    // ======================= Pass B: weights + PV =======================
    float of[4][4];
#pragma unroll
    for (int nt = 0; nt < 4; nt++)
#pragma unroll
        for (int j = 0; j < 4; j++) of[nt][j] = 0.f;

    float* Pp = sh + OFF_P;

#pragma unroll 1
    for (int kt = 0; kt < NKT; ++kt) {
        const unsigned cd = (kt & 1) ? APD : 0u;
        const bool haveK = (kt + 1 < NKT);

        // top: issue V(kt) [group V], then K(kt+1) -> alt buffer [group K]
        {
            const float* vsrc = vg + (size_t)kt * 64 * DMODEL;
#pragma unroll
            for (int i = 0; i < 4; i++) {
                int f = tid + 256 * i;
                int row = f >> 4, c4 = f & 15;
                CP16(uVst + (unsigned)(row * VSTR + c4 * 4) * 4,
                     vsrc + (size_t)row * DMODEL + c4 * 4);
            }
            CP_COMMIT();
        }
        if (haveK) {
            const unsigned nd = ((kt + 1) & 1) ? APD : 0u;
            const float* ksrc = kg + (size_t)(kt + 1) * 64 * DMODEL;
#pragma unroll
            for (int i = 0; i < 4; i++) {
                int f = tid + 256 * i;
                int row = f >> 4, c4 = f & 15;
                CP16(uKst + nd + (unsigned)(row * QSTR + c4 * 4) * 4,
                     ksrc + (size_t)row * DMODEL + c4 * 4);
            }
            CP_COMMIT();
        }

        // QK from K(kt) (current buffer; landed before this iteration)
        float sf[4][4];
#pragma unroll
        for (int nt = 0; nt < 4; nt++)
#pragma unroll
            for (int j = 0; j < 4; j++) sf[nt][j] = 0.f;
#pragma unroll
        for (int kq = 0; kq < 8; kq++) {
            unsigned bF[4];
            ldsm4(bF, uK[0] + cd + kq * 32);
            mma_tf32(sf[0], qf[kq], bF[0], bF[1]);
            mma_tf32(sf[1], qf[kq], bF[2], bF[3]);
            ldsm4(bF, uK[1] + cd + kq * 32);
            mma_tf32(sf[2], qf[kq], bF[0], bF[1]);
            mma_tf32(sf[3], qf[kq], bF[2], bF[3]);
        }

        // weights + P store (block-shared, stride 68)
#pragma unroll
        for (int nt = 0; nt < 4; nt++) {
            int col = nw + nt * 8 + 2 * c;
            float2 mv = __ldg(&mb2[(kt * 64 + col) >> 1]);
            float mk0 = mv.x * -1e9f, mk1 = mv.y * -1e9f;
            float p0 = __expf(sf[nt][0] + mk0) * il0;
            float p1 = __expf(sf[nt][1] + mk1) * il0;
            float p2 = __expf(sf[nt][2] + mk0) * il1;
            float p3 = __expf(sf[nt][3] + mk1) * il1;
            float* wp = wb + (size_t)(mw + r) * SEQ + kt * 64 + col;
            *(float2*)wp = make_float2(p0, p1);
            *(float2*)(wp + 8 * SEQ) = make_float2(p2, p3);
            *(float2*)&Pp[(mw + r) * QSTR + col] =
                make_float2(to_tf32(p0), to_tf32(p1));
            *(float2*)&Pp[(mw + r + 8) * QSTR + col] =
                make_float2(to_tf32(p2), to_tf32(p3));
        }

        // mid: drain V group only (K group keeps flying through PV)
        if (haveK) { CP_WAIT1(); } else { CP_WAIT0(); }
        __syncthreads();   // V(kt) + P visible; QK reads of K done

        // PV: O(16 rows x 32 dims) += P(16x64) @ V(64x32)
        const float* Vs_ = sh + OFF_V;
#pragma unroll
        for (int ks = 0; ks < 64; ks += 8) {
            unsigned a[4];
            ldsm4(a, uPfr + ks * 4);
            const float* Vr0 = Vs_ + (ks + c) * VSTR + nw;
            const float* Vr1 = Vs_ + (ks + c + 4) * VSTR + nw;
#pragma unroll
            for (int nt = 0; nt < 4; nt++) {
                unsigned b0 = f2u(Vr0[nt * 8 + r]);
                unsigned b1 = f2u(Vr1[nt * 8 + r]);
                mma_tf32(of[nt], a, b0, b1);
            }
        }

        // end: drain K(kt+1); barrier frees V/P buffers for next tile
        if (haveK) {
            CP_WAIT0();
            __syncthreads();
        }
    }

    // direct O store
    float* ab = g_a + ((size_t)(b * SEQ + q0 + mw + r)) * DMODEL + h * DHEAD;
#pragma unroll
    for (int nt = 0; nt < 4; nt++) {
        int col = nw + nt * 8 + 2 * c;
        *(float2*)(ab + col) = make_float2(of[nt][0], of[nt][1]);
        *(float2*)(ab + (size_t)8 * DMODEL + col) =
            make_float2(of[nt][2], of[nt][3]);
    }
}

// ----------------------------------------------------------------------------
extern "C" void kernel_launch(void* const* d_in, const int* in_sizes, int n_in,
                              void* d_out, int out_size)
{
    const float* Q    = (const float*)d_in[0];
    const float* K    = (const float*)d_in[1];
    const float* V    = (const float*)d_in[2];
    const float* mask = (const float*)d_in[3];
    const float* Wq_w = (const float*)d_in[4];
    const float* Wq_b = (const float*)d_in[5];
    const float* Wk_w = (const float*)d_in[6];
    const float* Wk_b = (const float*)d_in[7];
    const float* Wv_w = (const float*)d_in[8];
    const float* Wv_b = (const float*)d_in[9];
    const float* Wo_w = (const float*)d_in[10];
    const float* Wo_b = (const float*)d_in[11];

    float* out = (float*)d_out;
    float* wts = out + (size_t)BATCH * SEQ * DMODEL;

    float *qb, *kb, *vb, *ab, *wt;
    cudaGetSymbolAddress((void**)&qb, g_q);
    cudaGetSymbolAddress((void**)&kb, g_k);
    cudaGetSymbolAddress((void**)&vb, g_v);
    cudaGetSymbolAddress((void**)&ab, g_a);
    cudaGetSymbolAddress((void**)&wt, g_wt);

    const int attn_smem = ATTN_SMEM_FLOATS * 4;   // 89088 B
    cudaFuncSetAttribute(attn11,
                         cudaFuncAttributeMaxDynamicSharedMemorySize, attn_smem);
    const int gemm_smem = GEMM5_SMEM_FLOATS * 4;  // 73728 B
    cudaFuncSetAttribute(gemm_qkv5,
                         cudaFuncAttributeMaxDynamicSharedMemorySize, gemm_smem);
    cudaFuncSetAttribute(gemm_o5,
                         cudaFuncAttributeMaxDynamicSharedMemorySize, gemm_smem);

    prep_w<<<dim3(16, 16, 4), dim3(32, 8)>>>(Wq_w, Wk_w, Wv_w, Wo_w, wt);

    dim3 gqkv(512 / 128, (BATCH * SEQ) / 128, 3);
    gemm_qkv5<<<gqkv, 256, gemm_smem>>>(Q, K, V, wt, Wq_b, Wk_b, Wv_b,
                                        qb, kb, vb);

    attn11<<<dim3(SEQ / 64, BATCH * NHEAD), 256, attn_smem>>>(mask, wts);

    dim3 gg(512 / 128, (BATCH * SEQ) / 128);
    gemm_o5<<<gg, 256, gemm_smem>>>(ab, wt + (size_t)3 * DMODEL * DMODEL,
                                    Wo_b, out);
}